// round 9
// baseline (speedup 1.0000x reference)
#include <cuda_runtime.h>
#include <cuda_bf16.h>
#include <math.h>

#define NB 8
#define SL 4096
#define HD 128
#define CCH 128
#define NCH (SL / CCH)   // 32
#define NT  (NB * NCH)   // 256 tiles

#define TPAD 136                     // padded bf16 row stride in smem tiles
#define TILE_BYTES (128 * TPAD * 2)  // 34816

typedef unsigned int u32;

// ---------------------------------------------------------------------------
// Scratch (no allocations allowed)
// ---------------------------------------------------------------------------
__device__ float g_cos[SL * HD];
__device__ float g_sin[SL * HD];
__device__ float g_h  [NT * HD * HD];           // per-chunk H[d][e] fp32
__device__ __nv_bfloat16 g_q_hi [NT * 16384];   // Qr  [t][d]
__device__ __nv_bfloat16 g_q_lo [NT * 16384];
__device__ __nv_bfloat16 g_kT_hi[NT * 16384];   // Kr^T [d][t]
__device__ __nv_bfloat16 g_kT_lo[NT * 16384];
__device__ __nv_bfloat16 g_v_hi [NT * 16384];   // V   [t][e]
__device__ __nv_bfloat16 g_v_lo [NT * 16384];
__device__ __nv_bfloat16 g_s_hi [NT * 16384];   // S excl prefix [d][e]
__device__ __nv_bfloat16 g_s_lo [NT * 16384];

// wid -> (p, nc); chosen so per-SMSP (wid%4) phase-B causal work is balanced
__device__ __constant__ int PTAB [16] = {1,3,3,0, 2,2,0,0, 0,1,1,2, 3,2,1,3};
__device__ __constant__ int NCTAB[16] = {0,0,1,0, 0,1,1,2, 3,1,2,2, 3,3,3,2};

// ---------------------------------------------------------------------------
// Primitives (baseline PTX, valid on plain sm_100)
// ---------------------------------------------------------------------------
__device__ __forceinline__ u32 smem_u32(const void* p) {
    u32 a;
    asm("{ .reg .u64 t; cvta.to.shared.u64 t, %1; cvt.u32.u64 %0, t; }"
        : "=r"(a) : "l"(p));
    return a;
}
__device__ __forceinline__ void ldsm4(u32* r, u32 a) {
    asm volatile("ldmatrix.sync.aligned.m8n8.x4.shared.b16 {%0,%1,%2,%3}, [%4];"
                 : "=r"(r[0]), "=r"(r[1]), "=r"(r[2]), "=r"(r[3]) : "r"(a));
}
__device__ __forceinline__ void ldsm4t(u32* r, u32 a) {
    asm volatile("ldmatrix.sync.aligned.m8n8.x4.trans.shared.b16 {%0,%1,%2,%3}, [%4];"
                 : "=r"(r[0]), "=r"(r[1]), "=r"(r[2]), "=r"(r[3]) : "r"(a));
}
__device__ __forceinline__ void mma_bf16(float* c, const u32* a, u32 b0, u32 b1) {
    asm volatile(
        "mma.sync.aligned.m16n8k16.row.col.f32.bf16.bf16.f32 "
        "{%0,%1,%2,%3},{%4,%5,%6,%7},{%8,%9},{%0,%1,%2,%3};"
        : "+f"(c[0]), "+f"(c[1]), "+f"(c[2]), "+f"(c[3])
        : "r"(a[0]), "r"(a[1]), "r"(a[2]), "r"(a[3]), "r"(b0), "r"(b1));
}
__device__ __forceinline__ void cp16(u32 dst, const void* src) {
    asm volatile("cp.async.cg.shared.global [%0], [%1], 16;"
                 :: "r"(dst), "l"(src) : "memory");
}
__device__ __forceinline__ void cp_commit() {
    asm volatile("cp.async.commit_group;" ::: "memory");
}
__device__ __forceinline__ void cp_wait0() {
    asm volatile("cp.async.wait_group 0;" ::: "memory");
}
__device__ __forceinline__ void cp_wait1() {
    asm volatile("cp.async.wait_group 1;" ::: "memory");
}
__device__ __forceinline__ u32 packbf(__nv_bfloat16 lo, __nv_bfloat16 hi) {
    return (u32)__bfloat16_as_ushort(hi) << 16 | (u32)__bfloat16_as_ushort(lo);
}
// split 8 floats -> hi/lo bf16, one uint4 store each
__device__ __forceinline__ void split8_store(__nv_bfloat16* ghi, __nv_bfloat16* glo,
                                             int off, const float* v) {
    u32 hw[4], lw[4];
    #pragma unroll
    for (int j = 0; j < 4; ++j) {
        float f0 = v[2 * j], f1 = v[2 * j + 1];
        __nv_bfloat16 h0 = __float2bfloat16(f0), h1 = __float2bfloat16(f1);
        hw[j] = packbf(h0, h1);
        lw[j] = packbf(__float2bfloat16(f0 - __bfloat162float(h0)),
                       __float2bfloat16(f1 - __bfloat162float(h1)));
    }
    *(uint4*)(ghi + off) = *(uint4*)hw;
    *(uint4*)(glo + off) = *(uint4*)lw;
}
__device__ __forceinline__ void ld8(float* r, const float* p) {
    *(float4*)r       = *(const float4*)p;
    *(float4*)(r + 4) = *(const float4*)(p + 4);
}

// gmem [128][128] bf16 tile -> padded smem tile, via cp.async (NTHR threads)
template<int NTHR>
__device__ __forceinline__ void copy_tile_async(u32 dst, const __nv_bfloat16* src,
                                                int tid) {
    #pragma unroll
    for (int i = 0; i < 2048 / NTHR; ++i) {
        int j = tid + i * NTHR;
        int row = j >> 4, col = j & 15;
        cp16(dst + row * (TPAD * 2) + col * 16, (const char*)src + j * 16);
    }
}

// ---------------------------------------------------------------------------
// Paired-row-group 3-term split GEMM, warp tile = rows {rA:16, rB:16} x 32
// cols (2 nt blocks at n0). Group A active for kk<=kkA, group B for kk<=kkB
// (kkA <= kkB). acc[8][4]: frag idx = grp*4 + nt*2 + h.
// ---------------------------------------------------------------------------
__device__ __forceinline__ void gemm_pair(u32 ah, u32 al, u32 bh, u32 bl,
                                          float acc[8][4], int rA, int rB, int n0,
                                          int kkA, int kkB, int lane) {
    int l15 = lane & 15, lhi = (lane >> 4) << 3;
    #pragma unroll 1
    for (int kk = 0; kk <= kkB; ++kk) {
        u32 arB = (u32)(((rB + l15) * TPAD + kk * 16 + lhi) * 2);
        u32 HB[4], LB[4];
        ldsm4(HB, ah + arB);
        ldsm4(LB, al + arB);
        bool doA = (kk <= kkA);
        u32 HA[4], LA[4];
        if (doA) {
            u32 arA = (u32)(((rA + l15) * TPAD + kk * 16 + lhi) * 2);
            ldsm4(HA, ah + arA);
            ldsm4(LA, al + arA);
        }
        #pragma unroll
        for (int nt = 0; nt < 2; ++nt) {
            u32 boff = (u32)(((kk * 16 + l15) * TPAD + n0 + nt * 16 + lhi) * 2);
            u32 B[4], C[4];
            ldsm4t(B, bh + boff);
            ldsm4t(C, bl + boff);
            float* b0 = acc[4 + nt * 2];
            float* b1 = acc[4 + nt * 2 + 1];
            mma_bf16(b0, HB, B[0], B[1]);
            mma_bf16(b1, HB, B[2], B[3]);
            mma_bf16(b0, HB, C[0], C[1]);
            mma_bf16(b1, HB, C[2], C[3]);
            mma_bf16(b0, LB, B[0], B[1]);
            mma_bf16(b1, LB, B[2], B[3]);
            if (doA) {
                float* a0 = acc[nt * 2];
                float* a1 = acc[nt * 2 + 1];
                mma_bf16(a0, HA, B[0], B[1]);
                mma_bf16(a1, HA, B[2], B[3]);
                mma_bf16(a0, HA, C[0], C[1]);
                mma_bf16(a1, HA, C[2], C[3]);
                mma_bf16(a0, LA, B[0], B[1]);
                mma_bf16(a1, LA, B[2], B[3]);
            }
        }
    }
}

// acc -> gmem fp32 [128][128] tile (row groups rA/rB, cols n0..n0+31)
__device__ __forceinline__ void epilogue(float* dst, float acc[8][4],
                                         int rA, int rB, int n0, int lane) {
    int rr = lane >> 2, cb = n0 + (lane & 3) * 2;
    #pragma unroll
    for (int grp = 0; grp < 2; ++grp) {
        int base = grp ? rB : rA;
        #pragma unroll
        for (int nt = 0; nt < 2; ++nt)
            #pragma unroll
            for (int h = 0; h < 2; ++h) {
                float* a = acc[grp * 4 + nt * 2 + h];
                int r0 = base + rr, c = cb + nt * 16 + h * 8;
                *(float2*)(dst + r0 * 128 + c)       = make_float2(a[0], a[1]);
                *(float2*)(dst + (r0 + 8) * 128 + c) = make_float2(a[2], a[3]);
            }
    }
}

// ---------------------------------------------------------------------------
// Kernel 0: RoPE cos/sin table (double internally)
// ---------------------------------------------------------------------------
__global__ void k_tab() {
    int s = blockIdx.x;
    int j = threadIdx.x;
    int j2 = j & 63;
    double inv = exp(-(double)j2 * (log(10000.0) / 64.0));
    double a = (double)s * inv;
    double sv, cv;
    sincos(a, &sv, &cv);
    g_cos[s * HD + j] = (float)cv;
    g_sin[s * HD + j] = (float)sv;
}

// ---------------------------------------------------------------------------
// Kernel 1: RoPE + split-bf16 (vectorized). Q -> g_q; K -> g_kT; V -> g_v.
// ---------------------------------------------------------------------------
__global__ void __launch_bounds__(256) k_rope(const float* __restrict__ Q,
                                              const float* __restrict__ K,
                                              const float* __restrict__ V) {
    extern __shared__ float buf[];   // [128][129]
    int b  = blockIdx.x >> 5;
    int ch = blockIdx.x & 31;
    int tid = threadIdx.x;
    int base  = (b * SL + ch * CCH) * HD;
    int tbase = blockIdx.x * 16384;

    #pragma unroll
    for (int i = 0; i < 8; ++i) {
        int u = tid + i * 256;
        int t = u >> 4;
        int d0 = (u & 15) << 3;
        int s = ch * CCH + t;
        int dp = d0 ^ 64;
        float sign = (d0 < 64) ? -1.f : 1.f;

        float cs[8], sn[8], q[8], qp[8], kx[8], kp[8], vv[8];
        ld8(cs, g_cos + s * HD + d0);
        ld8(sn, g_sin + s * HD + d0);
        ld8(q,  Q + base + t * HD + d0);
        ld8(qp, Q + base + t * HD + dp);
        ld8(kx, K + base + t * HD + d0);
        ld8(kp, K + base + t * HD + dp);
        ld8(vv, V + base + t * HD + d0);

        float qo[8], ko[8];
        #pragma unroll
        for (int j = 0; j < 8; ++j) {
            qo[j] = q[j]  * cs[j] + sign * qp[j] * sn[j];
            ko[j] = kx[j] * cs[j] + sign * kp[j] * sn[j];
        }
        split8_store(g_q_hi, g_q_lo, tbase + t * HD + d0, qo);
        split8_store(g_v_hi, g_v_lo, tbase + t * HD + d0, vv);
        #pragma unroll
        for (int j = 0; j < 8; ++j) buf[t * 129 + d0 + j] = ko[j];
    }
    __syncthreads();

    #pragma unroll
    for (int i = 0; i < 8; ++i) {
        int u = tid + i * 256;
        int d = u >> 4;
        int t0 = (u & 15) << 3;
        float kv[8];
        #pragma unroll
        for (int j = 0; j < 8; ++j) kv[j] = buf[(t0 + j) * 129 + d];
        split8_store(g_kT_hi, g_kT_lo, tbase + d * HD + t0, kv);
    }
}

// ---------------------------------------------------------------------------
// Kernel 2: per-chunk H[d][e] = sum_t Kr^T[d][t] * V[t][e]. Dense.
// 512 threads; warp (p,nc) tile = rows {16p, 16(7-p)} x cols 32nc.
// ---------------------------------------------------------------------------
__global__ void __launch_bounds__(512) k_h() {
    extern __shared__ char sm[];
    u32 sb = smem_u32(sm);
    int tile = blockIdx.x;
    int tid = threadIdx.x, lane = tid & 31, wid = tid >> 5;
    int p = wid >> 2, nc = wid & 3;
    int rA = 16 * p, rB = 16 * (7 - p), n0 = 32 * nc;
    int tbase = tile * 16384;

    copy_tile_async<512>(sb,                  g_kT_hi + tbase, tid);
    copy_tile_async<512>(sb + TILE_BYTES,     g_kT_lo + tbase, tid);
    copy_tile_async<512>(sb + 2 * TILE_BYTES, g_v_hi  + tbase, tid);
    copy_tile_async<512>(sb + 3 * TILE_BYTES, g_v_lo  + tbase, tid);
    cp_commit();
    cp_wait0();
    __syncthreads();

    float acc[8][4] = {};
    gemm_pair(sb, sb + TILE_BYTES, sb + 2 * TILE_BYTES, sb + 3 * TILE_BYTES,
              acc, rA, rB, n0, 7, 7, lane);
    epilogue(g_h + tbase, acc, rA, rB, n0, lane);
}

// ---------------------------------------------------------------------------
// Kernel 3: exclusive prefix scan of H over chunks -> split-bf16 S tiles.
// Vectorized: thread owns 4 consecutive e; float4 loads, uint2 stores.
// ---------------------------------------------------------------------------
__global__ void __launch_bounds__(128) k_scan() {
    int b = blockIdx.x;
    int d = blockIdx.y * 4 + (threadIdx.x >> 5);
    int e0 = (threadIdx.x & 31) * 4;
    int o = d * 128 + e0;
    float4 run = make_float4(0.f, 0.f, 0.f, 0.f);
    #pragma unroll 4
    for (int i = 0; i < NCH; ++i) {
        int tb = (b * NCH + i) * 16384;
        float4 v = *(const float4*)(g_h + tb + o);
        __nv_bfloat16 h0 = __float2bfloat16(run.x);
        __nv_bfloat16 h1 = __float2bfloat16(run.y);
        __nv_bfloat16 h2 = __float2bfloat16(run.z);
        __nv_bfloat16 h3 = __float2bfloat16(run.w);
        uint2 hw, lw;
        hw.x = packbf(h0, h1);
        hw.y = packbf(h2, h3);
        lw.x = packbf(__float2bfloat16(run.x - __bfloat162float(h0)),
                      __float2bfloat16(run.y - __bfloat162float(h1)));
        lw.y = packbf(__float2bfloat16(run.z - __bfloat162float(h2)),
                      __float2bfloat16(run.w - __bfloat162float(h3)));
        *(uint2*)(g_s_hi + tb + o) = hw;
        *(uint2*)(g_s_lo + tb + o) = lw;
        run.x += v.x; run.y += v.y; run.z += v.z; run.w += v.w;
    }
}

// ---------------------------------------------------------------------------
// Kernel 4: out = tril(Qr Kr^T) V + Qr S  per (b, chunk). 512 threads.
// Warp (p,nc) from LUT: rows {16p, 16(7-p)}, cols 32nc..32nc+31.
// Slots: s0/s1 = Q, s2/s3 = KT -> E, s4/s5 = S -> V.
// Phase B computes only needed E blocks (block j=2nc+nt needed iff j <= g);
// phase C k-limits (kkA=p, kkB=7-p) exactly cover those blocks.
// ---------------------------------------------------------------------------
__global__ void __launch_bounds__(512) k_out(float* __restrict__ out) {
    extern __shared__ char sm[];
    u32 sb = smem_u32(sm);
    int tile = blockIdx.x;
    int tid = threadIdx.x, lane = tid & 31, wid = tid >> 5;
    int qb = tile * 16384;
    int p = PTAB[wid], nc = NCTAB[wid];
    int rA = 16 * p, rB = 16 * (7 - p), n0 = 32 * nc;
    int l15 = lane & 15, lhi = (lane >> 4) << 3;

    u32 s0 = sb, s1 = sb + TILE_BYTES, s2 = sb + 2 * TILE_BYTES,
        s3 = sb + 3 * TILE_BYTES, s4 = sb + 4 * TILE_BYTES, s5 = sb + 5 * TILE_BYTES;

    // g1: Q + S (phase A operands)
    copy_tile_async<512>(s0, g_q_hi + qb, tid);
    copy_tile_async<512>(s1, g_q_lo + qb, tid);
    copy_tile_async<512>(s4, g_s_hi + qb, tid);
    copy_tile_async<512>(s5, g_s_lo + qb, tid);
    cp_commit();
    // g2: KT (streams under phase A)
    copy_tile_async<512>(s2, g_kT_hi + qb, tid);
    copy_tile_async<512>(s3, g_kT_lo + qb, tid);
    cp_commit();

    cp_wait1();
    __syncthreads();

    // phase A: O = Qr @ S  (dense)
    float oacc[8][4] = {};
    gemm_pair(s0, s1, s4, s5, oacc, rA, rB, n0, 7, 7, lane);

    cp_wait0();        // KT arrived
    __syncthreads();   // all warps done reading S; KT visible

    // g3: V into S slots (streams under phase B)
    copy_tile_async<512>(s4, g_v_hi + qb, tid);
    copy_tile_async<512>(s5, g_v_lo + qb, tid);
    cp_commit();

    // phase B: E = Qr @ Kr^T, only needed blocks.
    // ntA/ntB = # of this warp's 16-col blocks needed for groups A/B.
    int ntA = p + 1 - 2 * nc;  ntA = ntA < 0 ? 0 : (ntA > 2 ? 2 : ntA);
    int ntB = 8 - p - 2 * nc;  ntB = ntB < 0 ? 0 : (ntB > 2 ? 2 : ntB);
    float eacc[8][4] = {};
    if (ntA | ntB) {
        #pragma unroll 1
        for (int kk = 0; kk < 8; ++kk) {
            u32 HA[4], LA[4], HB[4], LB[4];
            if (ntA) {
                u32 ar = (u32)(((rA + l15) * TPAD + kk * 16 + lhi) * 2);
                ldsm4(HA, s0 + ar);
                ldsm4(LA, s1 + ar);
            }
            if (ntB) {
                u32 ar = (u32)(((rB + l15) * TPAD + kk * 16 + lhi) * 2);
                ldsm4(HB, s0 + ar);
                ldsm4(LB, s1 + ar);
            }
            #pragma unroll
            for (int nt = 0; nt < 2; ++nt) {
                bool dA = nt < ntA, dB = nt < ntB;
                if (!(dA || dB)) continue;
                u32 boff = (u32)(((kk * 16 + l15) * TPAD + n0 + nt * 16 + lhi) * 2);
                u32 B[4], C[4];
                ldsm4t(B, s2 + boff);
                ldsm4t(C, s3 + boff);
                if (dA) {
                    float* a0 = eacc[nt * 2];
                    float* a1 = eacc[nt * 2 + 1];
                    mma_bf16(a0, HA, B[0], B[1]);
                    mma_bf16(a1, HA, B[2], B[3]);
                    mma_bf16(a0, HA, C[0], C[1]);
                    mma_bf16(a1, HA, C[2], C[3]);
                    mma_bf16(a0, LA, B[0], B[1]);
                    mma_bf16(a1, LA, B[2], B[3]);
                }
                if (dB) {
                    float* b0 = eacc[4 + nt * 2];
                    float* b1 = eacc[4 + nt * 2 + 1];
                    mma_bf16(b0, HB, B[0], B[1]);
                    mma_bf16(b1, HB, B[2], B[3]);
                    mma_bf16(b0, HB, C[0], C[1]);
                    mma_bf16(b1, HB, C[2], C[3]);
                    mma_bf16(b0, LB, B[0], B[1]);
                    mma_bf16(b1, LB, B[2], B[3]);
                }
            }
        }
    }
    __syncthreads();   // all warps done reading KT slots

    // mask (causal) + split E -> KT slots (bf16 hi/lo); only computed blocks
    {
        char* eh = (char*)sm + 2 * TILE_BYTES;
        char* el = (char*)sm + 3 * TILE_BYTES;
        int rr = lane >> 2, cb = n0 + (lane & 3) * 2;
        #pragma unroll
        for (int grp = 0; grp < 2; ++grp) {
            int base = grp ? rB : rA;
            int ncnt = grp ? ntB : ntA;
            for (int nt = 0; nt < ncnt; ++nt)
                #pragma unroll
                for (int h = 0; h < 2; ++h) {
                    float* a = eacc[grp * 4 + nt * 2 + h];
                    int rr0 = base + rr, rr1 = rr0 + 8;
                    int c = cb + nt * 16 + h * 8;
                    float v0 = (c     <= rr0) ? a[0] : 0.f;
                    float v1 = (c + 1 <= rr0) ? a[1] : 0.f;
                    float v2 = (c     <= rr1) ? a[2] : 0.f;
                    float v3 = (c + 1 <= rr1) ? a[3] : 0.f;
                    __nv_bfloat16 h0 = __float2bfloat16(v0);
                    __nv_bfloat16 h1 = __float2bfloat16(v1);
                    __nv_bfloat16 h2 = __float2bfloat16(v2);
                    __nv_bfloat16 h3 = __float2bfloat16(v3);
                    *(u32*)(eh + (rr0 * TPAD + c) * 2) = packbf(h0, h1);
                    *(u32*)(eh + (rr1 * TPAD + c) * 2) = packbf(h2, h3);
                    *(u32*)(el + (rr0 * TPAD + c) * 2) =
                        packbf(__float2bfloat16(v0 - __bfloat162float(h0)),
                               __float2bfloat16(v1 - __bfloat162float(h1)));
                    *(u32*)(el + (rr1 * TPAD + c) * 2) =
                        packbf(__float2bfloat16(v2 - __bfloat162float(h2)),
                               __float2bfloat16(v3 - __bfloat162float(h3)));
                }
        }
    }
    cp_wait0();        // V arrived
    __syncthreads();   // E + V visible to all warps

    // phase C: O += E @ V  (balanced causal: group A kk<=p, group B kk<=7-p)
    gemm_pair(s2, s3, s4, s5, oacc, rA, rB, n0, p, 7 - p, lane);

    epilogue(out + qb, oacc, rA, rB, n0, lane);
}

// ---------------------------------------------------------------------------
extern "C" void kernel_launch(void* const* d_in, const int* in_sizes, int n_in,
                              void* d_out, int out_size) {
    (void)in_sizes; (void)n_in; (void)out_size;
    const float* Q = (const float*)d_in[0];
    const float* K = (const float*)d_in[1];
    const float* V = (const float*)d_in[2];
    float* out = (float*)d_out;

    cudaFuncSetAttribute(k_rope, cudaFuncAttributeMaxDynamicSharedMemorySize, 66048);
    cudaFuncSetAttribute(k_h,    cudaFuncAttributeMaxDynamicSharedMemorySize, 4 * TILE_BYTES);
    cudaFuncSetAttribute(k_out,  cudaFuncAttributeMaxDynamicSharedMemorySize, 6 * TILE_BYTES);

    k_tab <<<SL, HD>>>();
    k_rope<<<NT, 256, 66048>>>(Q, K, V);
    k_h   <<<NT, 512, 4 * TILE_BYTES>>>();
    k_scan<<<dim3(NB, 32), 128>>>();
    k_out <<<NT, 512, 6 * TILE_BYTES>>>(out);
}

// round 10
// speedup vs baseline: 1.0435x; 1.0435x over previous
#include <cuda_runtime.h>
#include <cuda_bf16.h>
#include <math.h>

#define NB 8
#define SL 4096
#define HD 128
#define CCH 128
#define NCH (SL / CCH)   // 32
#define NT  (NB * NCH)   // 256 tiles

#define TPAD 136                     // padded bf16 row stride in smem tiles
#define TILE_BYTES (128 * TPAD * 2)  // 34816

typedef unsigned int u32;

// ---------------------------------------------------------------------------
// Scratch (no allocations allowed)
// ---------------------------------------------------------------------------
__device__ float g_cos[SL * HD];
__device__ float g_sin[SL * HD];
__device__ float g_h  [NT * HD * HD];           // per-chunk H[d][e] fp32
__device__ __nv_bfloat16 g_q_hi [NT * 16384];   // Qr  [t][d]
__device__ __nv_bfloat16 g_q_lo [NT * 16384];
__device__ __nv_bfloat16 g_kT_hi[NT * 16384];   // Kr^T [d][t]
__device__ __nv_bfloat16 g_kT_lo[NT * 16384];
__device__ __nv_bfloat16 g_v_hi [NT * 16384];   // V   [t][e]
__device__ __nv_bfloat16 g_v_lo [NT * 16384];
__device__ __nv_bfloat16 g_s_hi [NT * 16384];   // S excl prefix [d][e]
__device__ __nv_bfloat16 g_s_lo [NT * 16384];

// Phase-B unit LUT: 36 causal E blocks (g,j), j<=g, spread so max 3 per warp.
__device__ __constant__ int UN[16]    = {3,3,2,3,2,2,2,2,2,3,2,2,2,2,3,1};
__device__ __constant__ int UG[16][3] = {{7,7,7},{7,7,7},{7,7,7},{6,6,6},
                                         {6,6,6},{6,6,6},{5,5,5},{5,5,5},
                                         {5,5,5},{4,4,4},{4,4,4},{3,3,3},
                                         {3,3,3},{2,2,2},{2,1,1},{0,0,0}};
__device__ __constant__ int UJ[16][3] = {{0,1,2},{3,4,5},{6,7,7},{0,1,2},
                                         {3,4,4},{5,6,6},{0,1,1},{2,3,3},
                                         {4,5,5},{0,1,2},{3,4,4},{0,1,1},
                                         {2,3,3},{0,1,1},{2,0,1},{0,0,0}};

// ---------------------------------------------------------------------------
// Primitives (baseline PTX, valid on plain sm_100)
// ---------------------------------------------------------------------------
__device__ __forceinline__ u32 smem_u32(const void* p) {
    u32 a;
    asm("{ .reg .u64 t; cvta.to.shared.u64 t, %1; cvt.u32.u64 %0, t; }"
        : "=r"(a) : "l"(p));
    return a;
}
__device__ __forceinline__ void ldsm4(u32* r, u32 a) {
    asm volatile("ldmatrix.sync.aligned.m8n8.x4.shared.b16 {%0,%1,%2,%3}, [%4];"
                 : "=r"(r[0]), "=r"(r[1]), "=r"(r[2]), "=r"(r[3]) : "r"(a));
}
__device__ __forceinline__ void ldsm4t(u32* r, u32 a) {
    asm volatile("ldmatrix.sync.aligned.m8n8.x4.trans.shared.b16 {%0,%1,%2,%3}, [%4];"
                 : "=r"(r[0]), "=r"(r[1]), "=r"(r[2]), "=r"(r[3]) : "r"(a));
}
__device__ __forceinline__ void mma_bf16(float* c, const u32* a, u32 b0, u32 b1) {
    asm volatile(
        "mma.sync.aligned.m16n8k16.row.col.f32.bf16.bf16.f32 "
        "{%0,%1,%2,%3},{%4,%5,%6,%7},{%8,%9},{%0,%1,%2,%3};"
        : "+f"(c[0]), "+f"(c[1]), "+f"(c[2]), "+f"(c[3])
        : "r"(a[0]), "r"(a[1]), "r"(a[2]), "r"(a[3]), "r"(b0), "r"(b1));
}
__device__ __forceinline__ void cp16(u32 dst, const void* src) {
    asm volatile("cp.async.cg.shared.global [%0], [%1], 16;"
                 :: "r"(dst), "l"(src) : "memory");
}
__device__ __forceinline__ void cp_commit() {
    asm volatile("cp.async.commit_group;" ::: "memory");
}
__device__ __forceinline__ void cp_wait0() {
    asm volatile("cp.async.wait_group 0;" ::: "memory");
}
__device__ __forceinline__ void cp_wait1() {
    asm volatile("cp.async.wait_group 1;" ::: "memory");
}
__device__ __forceinline__ u32 packbf(__nv_bfloat16 lo, __nv_bfloat16 hi) {
    return (u32)__bfloat16_as_ushort(hi) << 16 | (u32)__bfloat16_as_ushort(lo);
}
__device__ __forceinline__ void split_store(__nv_bfloat16* hi, __nv_bfloat16* lo,
                                            int off, float v) {
    __nv_bfloat16 h = __float2bfloat16(v);
    hi[off] = h;
    lo[off] = __float2bfloat16(v - __bfloat162float(h));
}
// split 8 floats -> hi/lo bf16, one uint4 store each
__device__ __forceinline__ void split8_store(__nv_bfloat16* ghi, __nv_bfloat16* glo,
                                             int off, const float* v) {
    u32 hw[4], lw[4];
    #pragma unroll
    for (int j = 0; j < 4; ++j) {
        float f0 = v[2 * j], f1 = v[2 * j + 1];
        __nv_bfloat16 h0 = __float2bfloat16(f0), h1 = __float2bfloat16(f1);
        hw[j] = packbf(h0, h1);
        lw[j] = packbf(__float2bfloat16(f0 - __bfloat162float(h0)),
                       __float2bfloat16(f1 - __bfloat162float(h1)));
    }
    *(uint4*)(ghi + off) = *(uint4*)hw;
    *(uint4*)(glo + off) = *(uint4*)lw;
}
__device__ __forceinline__ void ld8(float* r, const float* p) {
    *(float4*)r       = *(const float4*)p;
    *(float4*)(r + 4) = *(const float4*)(p + 4);
}

// gmem [128][128] bf16 tile -> padded smem tile, via cp.async (NTHR threads)
template<int NTHR>
__device__ __forceinline__ void copy_tile_async(u32 dst, const __nv_bfloat16* src,
                                                int tid) {
    #pragma unroll
    for (int i = 0; i < 2048 / NTHR; ++i) {
        int j = tid + i * NTHR;
        int row = j >> 4, col = j & 15;
        cp16(dst + row * (TPAD * 2) + col * 16, (const char*)src + j * 16);
    }
}

// ---------------------------------------------------------------------------
// Paired-row-group 3-term split GEMM, warp tile = rows {rA:16, rB:16} x 32
// cols (2 nt blocks at n0). Group A active for kk<=kkA, group B for kk<=kkB
// (kkA <= kkB). acc[8][4]: frag idx = grp*4 + nt*2 + h.
// ---------------------------------------------------------------------------
__device__ __forceinline__ void gemm_pair(u32 ah, u32 al, u32 bh, u32 bl,
                                          float acc[8][4], int rA, int rB, int n0,
                                          int kkA, int kkB, int lane) {
    int l15 = lane & 15, lhi = (lane >> 4) << 3;
    #pragma unroll 1
    for (int kk = 0; kk <= kkB; ++kk) {
        u32 arB = (u32)(((rB + l15) * TPAD + kk * 16 + lhi) * 2);
        u32 HB[4], LB[4];
        ldsm4(HB, ah + arB);
        ldsm4(LB, al + arB);
        bool doA = (kk <= kkA);
        u32 HA[4], LA[4];
        if (doA) {
            u32 arA = (u32)(((rA + l15) * TPAD + kk * 16 + lhi) * 2);
            ldsm4(HA, ah + arA);
            ldsm4(LA, al + arA);
        }
        #pragma unroll
        for (int nt = 0; nt < 2; ++nt) {
            u32 boff = (u32)(((kk * 16 + l15) * TPAD + n0 + nt * 16 + lhi) * 2);
            u32 B[4], C[4];
            ldsm4t(B, bh + boff);
            ldsm4t(C, bl + boff);
            float* b0 = acc[4 + nt * 2];
            float* b1 = acc[4 + nt * 2 + 1];
            mma_bf16(b0, HB, B[0], B[1]);
            mma_bf16(b1, HB, B[2], B[3]);
            mma_bf16(b0, HB, C[0], C[1]);
            mma_bf16(b1, HB, C[2], C[3]);
            mma_bf16(b0, LB, B[0], B[1]);
            mma_bf16(b1, LB, B[2], B[3]);
            if (doA) {
                float* a0 = acc[nt * 2];
                float* a1 = acc[nt * 2 + 1];
                mma_bf16(a0, HA, B[0], B[1]);
                mma_bf16(a1, HA, B[2], B[3]);
                mma_bf16(a0, HA, C[0], C[1]);
                mma_bf16(a1, HA, C[2], C[3]);
                mma_bf16(a0, LA, B[0], B[1]);
                mma_bf16(a1, LA, B[2], B[3]);
            }
        }
    }
}

// acc -> gmem fp32 [128][128] tile (row groups rA/rB, cols n0..n0+31)
__device__ __forceinline__ void epilogue(float* dst, float acc[8][4],
                                         int rA, int rB, int n0, int lane) {
    int rr = lane >> 2, cb = n0 + (lane & 3) * 2;
    #pragma unroll
    for (int grp = 0; grp < 2; ++grp) {
        int base = grp ? rB : rA;
        #pragma unroll
        for (int nt = 0; nt < 2; ++nt)
            #pragma unroll
            for (int h = 0; h < 2; ++h) {
                float* a = acc[grp * 4 + nt * 2 + h];
                int r0 = base + rr, c = cb + nt * 16 + h * 8;
                *(float2*)(dst + r0 * 128 + c)       = make_float2(a[0], a[1]);
                *(float2*)(dst + (r0 + 8) * 128 + c) = make_float2(a[2], a[3]);
            }
    }
}

// ---------------------------------------------------------------------------
// Kernel 0: RoPE cos/sin table. cos[s][d] == cos[s][d^64] -> 64 threads
// compute once, write both halves.
// ---------------------------------------------------------------------------
__global__ void k_tab() {
    int s = blockIdx.x;
    int j = threadIdx.x;   // 0..63
    double inv = exp(-(double)j * (log(10000.0) / 64.0));
    double a = (double)s * inv;
    double sv, cv;
    sincos(a, &sv, &cv);
    float cf = (float)cv, sf = (float)sv;
    g_cos[s * HD + j]      = cf;
    g_cos[s * HD + j + 64] = cf;
    g_sin[s * HD + j]      = sf;
    g_sin[s * HD + j + 64] = sf;
}

// ---------------------------------------------------------------------------
// Kernel 1: RoPE + split-bf16 (vectorized). Q -> g_q; K -> g_kT; V -> g_v.
// ---------------------------------------------------------------------------
__global__ void __launch_bounds__(256) k_rope(const float* __restrict__ Q,
                                              const float* __restrict__ K,
                                              const float* __restrict__ V) {
    extern __shared__ float buf[];   // [128][129]
    int b  = blockIdx.x >> 5;
    int ch = blockIdx.x & 31;
    int tid = threadIdx.x;
    int base  = (b * SL + ch * CCH) * HD;
    int tbase = blockIdx.x * 16384;

    #pragma unroll
    for (int i = 0; i < 8; ++i) {
        int u = tid + i * 256;
        int t = u >> 4;
        int d0 = (u & 15) << 3;
        int s = ch * CCH + t;
        int dp = d0 ^ 64;
        float sign = (d0 < 64) ? -1.f : 1.f;

        float cs[8], sn[8], q[8], qp[8], kx[8], kp[8], vv[8];
        ld8(cs, g_cos + s * HD + d0);
        ld8(sn, g_sin + s * HD + d0);
        ld8(q,  Q + base + t * HD + d0);
        ld8(qp, Q + base + t * HD + dp);
        ld8(kx, K + base + t * HD + d0);
        ld8(kp, K + base + t * HD + dp);
        ld8(vv, V + base + t * HD + d0);

        float qo[8], ko[8];
        #pragma unroll
        for (int j = 0; j < 8; ++j) {
            qo[j] = q[j]  * cs[j] + sign * qp[j] * sn[j];
            ko[j] = kx[j] * cs[j] + sign * kp[j] * sn[j];
        }
        split8_store(g_q_hi, g_q_lo, tbase + t * HD + d0, qo);
        split8_store(g_v_hi, g_v_lo, tbase + t * HD + d0, vv);
        #pragma unroll
        for (int j = 0; j < 8; ++j) buf[t * 129 + d0 + j] = ko[j];
    }
    __syncthreads();

    #pragma unroll
    for (int i = 0; i < 8; ++i) {
        int u = tid + i * 256;
        int d = u >> 4;
        int t0 = (u & 15) << 3;
        float kv[8];
        #pragma unroll
        for (int j = 0; j < 8; ++j) kv[j] = buf[(t0 + j) * 129 + d];
        split8_store(g_kT_hi, g_kT_lo, tbase + d * HD + t0, kv);
    }
}

// ---------------------------------------------------------------------------
// Kernel 2: per-chunk H[d][e] = sum_t Kr^T[d][t] * V[t][e]. Dense.
// 512 threads; warp (p,nc) tile = rows {16p, 16(7-p)} x cols 32nc.
// ---------------------------------------------------------------------------
__global__ void __launch_bounds__(512) k_h() {
    extern __shared__ char sm[];
    u32 sb = smem_u32(sm);
    int tile = blockIdx.x;
    int tid = threadIdx.x, lane = tid & 31, wid = tid >> 5;
    int p = wid >> 2, nc = wid & 3;
    int rA = 16 * p, rB = 16 * (7 - p), n0 = 32 * nc;
    int tbase = tile * 16384;

    copy_tile_async<512>(sb,                  g_kT_hi + tbase, tid);
    copy_tile_async<512>(sb + TILE_BYTES,     g_kT_lo + tbase, tid);
    copy_tile_async<512>(sb + 2 * TILE_BYTES, g_v_hi  + tbase, tid);
    copy_tile_async<512>(sb + 3 * TILE_BYTES, g_v_lo  + tbase, tid);
    cp_commit();
    cp_wait0();
    __syncthreads();

    float acc[8][4] = {};
    gemm_pair(sb, sb + TILE_BYTES, sb + 2 * TILE_BYTES, sb + 3 * TILE_BYTES,
              acc, rA, rB, n0, 7, 7, lane);
    epilogue(g_h + tbase, acc, rA, rB, n0, lane);
}

// ---------------------------------------------------------------------------
// Kernel 3: exclusive prefix scan of H over chunks -> split-bf16 S tiles.
// R8-proven form: 1024 blocks, thread = one column, full-MLP prefetch.
// ---------------------------------------------------------------------------
__global__ void __launch_bounds__(128) k_scan() {
    int b = blockIdx.x, d = blockIdx.y, e = threadIdx.x;
    float vals[NCH];
    #pragma unroll
    for (int i = 0; i < NCH; ++i)
        vals[i] = g_h[(b * NCH + i) * 16384 + d * 128 + e];
    int o = d * 128 + e;
    float run = 0.f;
    #pragma unroll
    for (int i = 0; i < NCH; ++i) {
        int tb = (b * NCH + i) * 16384;
        split_store(g_s_hi, g_s_lo, tb + o, run);
        run += vals[i];
    }
}

// ---------------------------------------------------------------------------
// Kernel 4: out = tril(Qr Kr^T) V + Qr S  per (b, chunk). 512 threads.
// Phase C warp (p = wid>>2, nc = wid&3): rows {16p, 16(7-p)}, cols 32nc
// (uniform 9/16 causal work). Phase B: 36 E blocks via per-warp-balanced LUT
// (max 3 units/warp vs dense 4). Slots: s0/s1 = Q, s2/s3 = KT -> E,
// s4/s5 = S -> V.
// ---------------------------------------------------------------------------
__global__ void __launch_bounds__(512) k_out(float* __restrict__ out) {
    extern __shared__ char sm[];
    u32 sb = smem_u32(sm);
    int tile = blockIdx.x;
    int tid = threadIdx.x, lane = tid & 31, wid = tid >> 5;
    int qb = tile * 16384;
    int p = wid >> 2, nc = wid & 3;
    int rA = 16 * p, rB = 16 * (7 - p), n0 = 32 * nc;
    int l15 = lane & 15, lhi = (lane >> 4) << 3;

    u32 s0 = sb, s1 = sb + TILE_BYTES, s2 = sb + 2 * TILE_BYTES,
        s3 = sb + 3 * TILE_BYTES, s4 = sb + 4 * TILE_BYTES, s5 = sb + 5 * TILE_BYTES;

    // g1: Q + S (phase A operands)
    copy_tile_async<512>(s0, g_q_hi + qb, tid);
    copy_tile_async<512>(s1, g_q_lo + qb, tid);
    copy_tile_async<512>(s4, g_s_hi + qb, tid);
    copy_tile_async<512>(s5, g_s_lo + qb, tid);
    cp_commit();
    // g2: KT (streams under phase A)
    copy_tile_async<512>(s2, g_kT_hi + qb, tid);
    copy_tile_async<512>(s3, g_kT_lo + qb, tid);
    cp_commit();

    cp_wait1();
    __syncthreads();

    // phase A: O = Qr @ S  (dense)
    float oacc[8][4] = {};
    gemm_pair(s0, s1, s4, s5, oacc, rA, rB, n0, 7, 7, lane);

    cp_wait0();        // KT arrived
    __syncthreads();   // all warps done reading S; KT visible

    // g3: V into S slots (streams under phase B)
    copy_tile_async<512>(s4, g_v_hi + qb, tid);
    copy_tile_async<512>(s5, g_v_lo + qb, tid);
    cp_commit();

    // phase B: E blocks (g,j) from balanced LUT; E = Qr @ Kr^T block-wise
    float eacc[3][2][4] = {};
    int un = UN[wid];
    #pragma unroll
    for (int u = 0; u < 3; ++u) {
        if (u < un) {
            int gU = UG[wid][u], jU = UJ[wid][u];
            int ra = 16 * gU, nb = 16 * jU;
            #pragma unroll 1
            for (int kk = 0; kk < 8; ++kk) {
                u32 ar = (u32)(((ra + l15) * TPAD + kk * 16 + lhi) * 2);
                u32 HA[4], LA[4];
                ldsm4(HA, s0 + ar);
                ldsm4(LA, s1 + ar);
                u32 boff = (u32)(((kk * 16 + l15) * TPAD + nb + lhi) * 2);
                u32 B[4], C[4];
                ldsm4t(B, s2 + boff);
                ldsm4t(C, s3 + boff);
                float* a0 = eacc[u][0];
                float* a1 = eacc[u][1];
                mma_bf16(a0, HA, B[0], B[1]);
                mma_bf16(a1, HA, B[2], B[3]);
                mma_bf16(a0, HA, C[0], C[1]);
                mma_bf16(a1, HA, C[2], C[3]);
                mma_bf16(a0, LA, B[0], B[1]);
                mma_bf16(a1, LA, B[2], B[3]);
            }
        }
    }
    __syncthreads();   // all warps done reading KT slots

    // mask (diag blocks only) + split E -> KT slots (bf16 hi/lo)
    {
        char* eh = (char*)sm + 2 * TILE_BYTES;
        char* el = (char*)sm + 3 * TILE_BYTES;
        #pragma unroll
        for (int u = 0; u < 3; ++u) {
            if (u < un) {
                int gU = UG[wid][u], jU = UJ[wid][u];
                int rr0 = 16 * gU + (lane >> 2), rr1 = rr0 + 8;
                bool diag = (jU == gU);
                #pragma unroll
                for (int h = 0; h < 2; ++h) {
                    float* a = eacc[u][h];
                    int c = 16 * jU + h * 8 + (lane & 3) * 2;
                    float v0 = (!diag || c     <= rr0) ? a[0] : 0.f;
                    float v1 = (!diag || c + 1 <= rr0) ? a[1] : 0.f;
                    float v2 = (!diag || c     <= rr1) ? a[2] : 0.f;
                    float v3 = (!diag || c + 1 <= rr1) ? a[3] : 0.f;
                    __nv_bfloat16 h0 = __float2bfloat16(v0);
                    __nv_bfloat16 h1 = __float2bfloat16(v1);
                    __nv_bfloat16 h2 = __float2bfloat16(v2);
                    __nv_bfloat16 h3 = __float2bfloat16(v3);
                    *(u32*)(eh + (rr0 * TPAD + c) * 2) = packbf(h0, h1);
                    *(u32*)(eh + (rr1 * TPAD + c) * 2) = packbf(h2, h3);
                    *(u32*)(el + (rr0 * TPAD + c) * 2) =
                        packbf(__float2bfloat16(v0 - __bfloat162float(h0)),
                               __float2bfloat16(v1 - __bfloat162float(h1)));
                    *(u32*)(el + (rr1 * TPAD + c) * 2) =
                        packbf(__float2bfloat16(v2 - __bfloat162float(h2)),
                               __float2bfloat16(v3 - __bfloat162float(h3)));
                }
            }
        }
    }
    cp_wait0();        // V arrived
    __syncthreads();   // E + V visible to all warps

    // phase C: O += E @ V  (balanced causal: group A kk<=p, group B kk<=7-p)
    gemm_pair(s2, s3, s4, s5, oacc, rA, rB, n0, p, 7 - p, lane);

    epilogue(out + qb, oacc, rA, rB, n0, lane);
}

// ---------------------------------------------------------------------------
extern "C" void kernel_launch(void* const* d_in, const int* in_sizes, int n_in,
                              void* d_out, int out_size) {
    (void)in_sizes; (void)n_in; (void)out_size;
    const float* Q = (const float*)d_in[0];
    const float* K = (const float*)d_in[1];
    const float* V = (const float*)d_in[2];
    float* out = (float*)d_out;

    cudaFuncSetAttribute(k_rope, cudaFuncAttributeMaxDynamicSharedMemorySize, 66048);
    cudaFuncSetAttribute(k_h,    cudaFuncAttributeMaxDynamicSharedMemorySize, 4 * TILE_BYTES);
    cudaFuncSetAttribute(k_out,  cudaFuncAttributeMaxDynamicSharedMemorySize, 6 * TILE_BYTES);

    k_tab <<<SL, 64>>>();
    k_rope<<<NT, 256, 66048>>>(Q, K, V);
    k_h   <<<NT, 512, 4 * TILE_BYTES>>>();
    k_scan<<<dim3(NB, HD), 128>>>();
    k_out <<<NT, 512, 6 * TILE_BYTES>>>(out);
}

// round 11
// speedup vs baseline: 1.0878x; 1.0425x over previous
#include <cuda_runtime.h>
#include <cuda_bf16.h>
#include <math.h>

#define NB 8
#define SL 4096
#define HD 128
#define CCH 128
#define NCH (SL / CCH)   // 32
#define NT  (NB * NCH)   // 256 tiles

#define TPAD 136                     // padded bf16 row stride in smem tiles
#define TILE_BYTES (128 * TPAD * 2)  // 34816

typedef unsigned int u32;

// ---------------------------------------------------------------------------
// Scratch (no allocations allowed)
// ---------------------------------------------------------------------------
__device__ float g_cos[SL * HD];
__device__ float g_sin[SL * HD];
__device__ float g_h  [NT * HD * HD];           // per-chunk H[d][e] fp32
__device__ __nv_bfloat16 g_q_hi [NT * 16384];   // Qr  [t][d]
__device__ __nv_bfloat16 g_q_lo [NT * 16384];
__device__ __nv_bfloat16 g_kT_hi[NT * 16384];   // Kr^T [d][t]
__device__ __nv_bfloat16 g_kT_lo[NT * 16384];
__device__ __nv_bfloat16 g_v_hi [NT * 16384];   // V   [t][e]
__device__ __nv_bfloat16 g_v_lo [NT * 16384];
__device__ __nv_bfloat16 g_s_hi [NT * 16384];   // S excl prefix [d][e]
__device__ __nv_bfloat16 g_s_lo [NT * 16384];

// Phase-B unit LUT: 36 causal E blocks (g,j), j<=g, spread so max 3 per warp.
__device__ __constant__ int UN[16]    = {3,3,2,3,2,2,2,2,2,3,2,2,2,2,3,1};
__device__ __constant__ int UG[16][3] = {{7,7,7},{7,7,7},{7,7,7},{6,6,6},
                                         {6,6,6},{6,6,6},{5,5,5},{5,5,5},
                                         {5,5,5},{4,4,4},{4,4,4},{3,3,3},
                                         {3,3,3},{2,2,2},{2,1,1},{0,0,0}};
__device__ __constant__ int UJ[16][3] = {{0,1,2},{3,4,5},{6,7,7},{0,1,2},
                                         {3,4,4},{5,6,6},{0,1,1},{2,3,3},
                                         {4,5,5},{0,1,2},{3,4,4},{0,1,1},
                                         {2,3,3},{0,1,1},{2,0,1},{0,0,0}};

// ---------------------------------------------------------------------------
// Primitives (baseline PTX, valid on plain sm_100)
// ---------------------------------------------------------------------------
__device__ __forceinline__ u32 smem_u32(const void* p) {
    u32 a;
    asm("{ .reg .u64 t; cvta.to.shared.u64 t, %1; cvt.u32.u64 %0, t; }"
        : "=r"(a) : "l"(p));
    return a;
}
__device__ __forceinline__ void ldsm4(u32* r, u32 a) {
    asm volatile("ldmatrix.sync.aligned.m8n8.x4.shared.b16 {%0,%1,%2,%3}, [%4];"
                 : "=r"(r[0]), "=r"(r[1]), "=r"(r[2]), "=r"(r[3]) : "r"(a));
}
__device__ __forceinline__ void ldsm4t(u32* r, u32 a) {
    asm volatile("ldmatrix.sync.aligned.m8n8.x4.trans.shared.b16 {%0,%1,%2,%3}, [%4];"
                 : "=r"(r[0]), "=r"(r[1]), "=r"(r[2]), "=r"(r[3]) : "r"(a));
}
__device__ __forceinline__ void mma_bf16(float* c, const u32* a, u32 b0, u32 b1) {
    asm volatile(
        "mma.sync.aligned.m16n8k16.row.col.f32.bf16.bf16.f32 "
        "{%0,%1,%2,%3},{%4,%5,%6,%7},{%8,%9},{%0,%1,%2,%3};"
        : "+f"(c[0]), "+f"(c[1]), "+f"(c[2]), "+f"(c[3])
        : "r"(a[0]), "r"(a[1]), "r"(a[2]), "r"(a[3]), "r"(b0), "r"(b1));
}
__device__ __forceinline__ void cp16(u32 dst, const void* src) {
    asm volatile("cp.async.cg.shared.global [%0], [%1], 16;"
                 :: "r"(dst), "l"(src) : "memory");
}
__device__ __forceinline__ void cp_commit() {
    asm volatile("cp.async.commit_group;" ::: "memory");
}
__device__ __forceinline__ void cp_wait0() {
    asm volatile("cp.async.wait_group 0;" ::: "memory");
}
__device__ __forceinline__ void cp_wait1() {
    asm volatile("cp.async.wait_group 1;" ::: "memory");
}
__device__ __forceinline__ u32 packbf(__nv_bfloat16 lo, __nv_bfloat16 hi) {
    return (u32)__bfloat16_as_ushort(hi) << 16 | (u32)__bfloat16_as_ushort(lo);
}
// split 8 floats -> hi/lo bf16, one uint4 store each
__device__ __forceinline__ void split8_store(__nv_bfloat16* ghi, __nv_bfloat16* glo,
                                             int off, const float* v) {
    u32 hw[4], lw[4];
    #pragma unroll
    for (int j = 0; j < 4; ++j) {
        float f0 = v[2 * j], f1 = v[2 * j + 1];
        __nv_bfloat16 h0 = __float2bfloat16(f0), h1 = __float2bfloat16(f1);
        hw[j] = packbf(h0, h1);
        lw[j] = packbf(__float2bfloat16(f0 - __bfloat162float(h0)),
                       __float2bfloat16(f1 - __bfloat162float(h1)));
    }
    *(uint4*)(ghi + off) = *(uint4*)hw;
    *(uint4*)(glo + off) = *(uint4*)lw;
}
__device__ __forceinline__ void ld8(float* r, const float* p) {
    *(float4*)r       = *(const float4*)p;
    *(float4*)(r + 4) = *(const float4*)(p + 4);
}

// gmem [128][128] bf16 tile -> padded smem tile, via cp.async (NTHR threads)
template<int NTHR>
__device__ __forceinline__ void copy_tile_async(u32 dst, const __nv_bfloat16* src,
                                                int tid) {
    #pragma unroll
    for (int i = 0; i < 2048 / NTHR; ++i) {
        int j = tid + i * NTHR;
        int row = j >> 4, col = j & 15;
        cp16(dst + row * (TPAD * 2) + col * 16, (const char*)src + j * 16);
    }
}

// ---------------------------------------------------------------------------
// Paired-row-group 3-term split GEMM, warp tile = rows {rA:16, rB:16} x 32
// cols (2 nt blocks at n0). Group A active for kk<=kkA, group B for kk<=kkB.
// acc[8][4]: frag idx = grp*4 + nt*2 + h.
// ---------------------------------------------------------------------------
__device__ __forceinline__ void gemm_pair(u32 ah, u32 al, u32 bh, u32 bl,
                                          float acc[8][4], int rA, int rB, int n0,
                                          int kkA, int kkB, int lane) {
    int l15 = lane & 15, lhi = (lane >> 4) << 3;
    #pragma unroll 1
    for (int kk = 0; kk <= kkB; ++kk) {
        u32 arB = (u32)(((rB + l15) * TPAD + kk * 16 + lhi) * 2);
        u32 HB[4], LB[4];
        ldsm4(HB, ah + arB);
        ldsm4(LB, al + arB);
        bool doA = (kk <= kkA);
        u32 HA[4], LA[4];
        if (doA) {
            u32 arA = (u32)(((rA + l15) * TPAD + kk * 16 + lhi) * 2);
            ldsm4(HA, ah + arA);
            ldsm4(LA, al + arA);
        }
        #pragma unroll
        for (int nt = 0; nt < 2; ++nt) {
            u32 boff = (u32)(((kk * 16 + l15) * TPAD + n0 + nt * 16 + lhi) * 2);
            u32 B[4], C[4];
            ldsm4t(B, bh + boff);
            ldsm4t(C, bl + boff);
            float* b0 = acc[4 + nt * 2];
            float* b1 = acc[4 + nt * 2 + 1];
            mma_bf16(b0, HB, B[0], B[1]);
            mma_bf16(b1, HB, B[2], B[3]);
            mma_bf16(b0, HB, C[0], C[1]);
            mma_bf16(b1, HB, C[2], C[3]);
            mma_bf16(b0, LB, B[0], B[1]);
            mma_bf16(b1, LB, B[2], B[3]);
            if (doA) {
                float* a0 = acc[nt * 2];
                float* a1 = acc[nt * 2 + 1];
                mma_bf16(a0, HA, B[0], B[1]);
                mma_bf16(a1, HA, B[2], B[3]);
                mma_bf16(a0, HA, C[0], C[1]);
                mma_bf16(a1, HA, C[2], C[3]);
                mma_bf16(a0, LA, B[0], B[1]);
                mma_bf16(a1, LA, B[2], B[3]);
            }
        }
    }
}

// 2-term variant: A split (ah, al), B single (bh). Used for phase C (E @ Vh).
__device__ __forceinline__ void gemm_pair2(u32 ah, u32 al, u32 bh,
                                           float acc[8][4], int rA, int rB, int n0,
                                           int kkA, int kkB, int lane) {
    int l15 = lane & 15, lhi = (lane >> 4) << 3;
    #pragma unroll 1
    for (int kk = 0; kk <= kkB; ++kk) {
        u32 arB = (u32)(((rB + l15) * TPAD + kk * 16 + lhi) * 2);
        u32 HB[4], LB[4];
        ldsm4(HB, ah + arB);
        ldsm4(LB, al + arB);
        bool doA = (kk <= kkA);
        u32 HA[4], LA[4];
        if (doA) {
            u32 arA = (u32)(((rA + l15) * TPAD + kk * 16 + lhi) * 2);
            ldsm4(HA, ah + arA);
            ldsm4(LA, al + arA);
        }
        #pragma unroll
        for (int nt = 0; nt < 2; ++nt) {
            u32 boff = (u32)(((kk * 16 + l15) * TPAD + n0 + nt * 16 + lhi) * 2);
            u32 B[4];
            ldsm4t(B, bh + boff);
            float* b0 = acc[4 + nt * 2];
            float* b1 = acc[4 + nt * 2 + 1];
            mma_bf16(b0, HB, B[0], B[1]);
            mma_bf16(b1, HB, B[2], B[3]);
            mma_bf16(b0, LB, B[0], B[1]);
            mma_bf16(b1, LB, B[2], B[3]);
            if (doA) {
                float* a0 = acc[nt * 2];
                float* a1 = acc[nt * 2 + 1];
                mma_bf16(a0, HA, B[0], B[1]);
                mma_bf16(a1, HA, B[2], B[3]);
                mma_bf16(a0, LA, B[0], B[1]);
                mma_bf16(a1, LA, B[2], B[3]);
            }
        }
    }
}

// acc -> gmem fp32 [128][128] tile (row groups rA/rB, cols n0..n0+31)
__device__ __forceinline__ void epilogue(float* dst, float acc[8][4],
                                         int rA, int rB, int n0, int lane) {
    int rr = lane >> 2, cb = n0 + (lane & 3) * 2;
    #pragma unroll
    for (int grp = 0; grp < 2; ++grp) {
        int base = grp ? rB : rA;
        #pragma unroll
        for (int nt = 0; nt < 2; ++nt)
            #pragma unroll
            for (int h = 0; h < 2; ++h) {
                float* a = acc[grp * 4 + nt * 2 + h];
                int r0 = base + rr, c = cb + nt * 16 + h * 8;
                *(float2*)(dst + r0 * 128 + c)       = make_float2(a[0], a[1]);
                *(float2*)(dst + (r0 + 8) * 128 + c) = make_float2(a[2], a[3]);
            }
    }
}

// ---------------------------------------------------------------------------
// Kernel 0: RoPE cos/sin table (64 threads/row; halves mirror at d^64)
// ---------------------------------------------------------------------------
__global__ void k_tab() {
    int s = blockIdx.x;
    int j = threadIdx.x;   // 0..63
    double inv = exp(-(double)j * (log(10000.0) / 64.0));
    double a = (double)s * inv;
    double sv, cv;
    sincos(a, &sv, &cv);
    float cf = (float)cv, sf = (float)sv;
    g_cos[s * HD + j]      = cf;
    g_cos[s * HD + j + 64] = cf;
    g_sin[s * HD + j]      = sf;
    g_sin[s * HD + j + 64] = sf;
}

// ---------------------------------------------------------------------------
// Kernel 1: RoPE + split-bf16 (vectorized). Q -> g_q; K -> g_kT; V -> g_v.
// ---------------------------------------------------------------------------
__global__ void __launch_bounds__(256) k_rope(const float* __restrict__ Q,
                                              const float* __restrict__ K,
                                              const float* __restrict__ V) {
    extern __shared__ float buf[];   // [128][129]
    int b  = blockIdx.x >> 5;
    int ch = blockIdx.x & 31;
    int tid = threadIdx.x;
    int base  = (b * SL + ch * CCH) * HD;
    int tbase = blockIdx.x * 16384;

    #pragma unroll
    for (int i = 0; i < 8; ++i) {
        int u = tid + i * 256;
        int t = u >> 4;
        int d0 = (u & 15) << 3;
        int s = ch * CCH + t;
        int dp = d0 ^ 64;
        float sign = (d0 < 64) ? -1.f : 1.f;

        float cs[8], sn[8], q[8], qp[8], kx[8], kp[8], vv[8];
        ld8(cs, g_cos + s * HD + d0);
        ld8(sn, g_sin + s * HD + d0);
        ld8(q,  Q + base + t * HD + d0);
        ld8(qp, Q + base + t * HD + dp);
        ld8(kx, K + base + t * HD + d0);
        ld8(kp, K + base + t * HD + dp);
        ld8(vv, V + base + t * HD + d0);

        float qo[8], ko[8];
        #pragma unroll
        for (int j = 0; j < 8; ++j) {
            qo[j] = q[j]  * cs[j] + sign * qp[j] * sn[j];
            ko[j] = kx[j] * cs[j] + sign * kp[j] * sn[j];
        }
        split8_store(g_q_hi, g_q_lo, tbase + t * HD + d0, qo);
        split8_store(g_v_hi, g_v_lo, tbase + t * HD + d0, vv);
        #pragma unroll
        for (int j = 0; j < 8; ++j) buf[t * 129 + d0 + j] = ko[j];
    }
    __syncthreads();

    #pragma unroll
    for (int i = 0; i < 8; ++i) {
        int u = tid + i * 256;
        int d = u >> 4;
        int t0 = (u & 15) << 3;
        float kv[8];
        #pragma unroll
        for (int j = 0; j < 8; ++j) kv[j] = buf[(t0 + j) * 129 + d];
        split8_store(g_kT_hi, g_kT_lo, tbase + d * HD + t0, kv);
    }
}

// ---------------------------------------------------------------------------
// Kernel 2: per-chunk H[d][e] = sum_t Kr^T[d][t] * V[t][e]. Dense, 3-term.
// Persistent: grid 128, each CTA does tiles (bx, bx+128) with KT prefetch.
// smem 6 slots: a0/a1 = KT1, a2/a3 = V (double-buffered), p0/p1 = KT2.
// ---------------------------------------------------------------------------
__global__ void __launch_bounds__(512) k_h() {
    extern __shared__ char sm[];
    u32 sb = smem_u32(sm);
    int tid = threadIdx.x, lane = tid & 31, wid = tid >> 5;
    int p = wid >> 2, nc = wid & 3;
    int rA = 16 * p, rB = 16 * (7 - p), n0 = 32 * nc;
    int t1 = blockIdx.x, t2 = blockIdx.x + 128;
    int tb1 = t1 * 16384, tb2 = t2 * 16384;

    u32 a0 = sb, a1 = sb + TILE_BYTES, a2 = sb + 2 * TILE_BYTES,
        a3 = sb + 3 * TILE_BYTES, p0 = sb + 4 * TILE_BYTES, p1 = sb + 5 * TILE_BYTES;

    // g1: tile-1 operands
    copy_tile_async<512>(a0, g_kT_hi + tb1, tid);
    copy_tile_async<512>(a1, g_kT_lo + tb1, tid);
    copy_tile_async<512>(a2, g_v_hi  + tb1, tid);
    copy_tile_async<512>(a3, g_v_lo  + tb1, tid);
    cp_commit();
    // g2: tile-2 KT prefetch (streams under tile-1 gemm)
    copy_tile_async<512>(p0, g_kT_hi + tb2, tid);
    copy_tile_async<512>(p1, g_kT_lo + tb2, tid);
    cp_commit();

    cp_wait1();
    __syncthreads();

    float acc[8][4] = {};
    gemm_pair(a0, a1, a2, a3, acc, rA, rB, n0, 7, 7, lane);
    epilogue(g_h + tb1, acc, rA, rB, n0, lane);
    __syncthreads();   // all warps done reading V slots

    // tile-2 V into V slots
    copy_tile_async<512>(a2, g_v_hi + tb2, tid);
    copy_tile_async<512>(a3, g_v_lo + tb2, tid);
    cp_commit();
    cp_wait0();
    __syncthreads();

    float acc2[8][4] = {};
    gemm_pair(p0, p1, a2, a3, acc2, rA, rB, n0, 7, 7, lane);
    epilogue(g_h + tb2, acc2, rA, rB, n0, lane);
}

// ---------------------------------------------------------------------------
// Kernel 3: exclusive prefix scan of H -> split-bf16 S tiles.
// Thread owns a column PAIR (u32 packed stores); full-MLP prefetch kept.
// ---------------------------------------------------------------------------
__global__ void __launch_bounds__(128) k_scan() {
    int b = blockIdx.x;
    int d = blockIdx.y * 2 + (threadIdx.x >> 6);
    int e0 = (threadIdx.x & 63) * 2;
    int o = d * 128 + e0;
    float2 vals[NCH];
    #pragma unroll
    for (int i = 0; i < NCH; ++i)
        vals[i] = *(const float2*)(g_h + (b * NCH + i) * 16384 + o);
    float2 run = make_float2(0.f, 0.f);
    #pragma unroll
    for (int i = 0; i < NCH; ++i) {
        int tb = (b * NCH + i) * 16384;
        __nv_bfloat16 h0 = __float2bfloat16(run.x);
        __nv_bfloat16 h1 = __float2bfloat16(run.y);
        *(u32*)(g_s_hi + tb + o) = packbf(h0, h1);
        *(u32*)(g_s_lo + tb + o) =
            packbf(__float2bfloat16(run.x - __bfloat162float(h0)),
                   __float2bfloat16(run.y - __bfloat162float(h1)));
        run.x += vals[i].x;
        run.y += vals[i].y;
    }
}

// ---------------------------------------------------------------------------
// Kernel 4: out = tril(Qr Kr^T) V + Qr S. Persistent: grid 128, 2 tiles/CTA.
// Slots: s0/s1 = Q (reused across tiles), s2/s3 = KT -> E, uSh/uSl = S -> Vh
// (roles swap between tiles). Phase C = 2-term (Eh+El) @ Vh (V_lo dropped).
// Cross-tile prefetch: during tile-1 E-split: Q2 + S2h; after C: S2l + KT2.
// ---------------------------------------------------------------------------
__global__ void __launch_bounds__(512) k_out(float* __restrict__ out) {
    extern __shared__ char sm[];
    u32 sb = smem_u32(sm);
    int tid = threadIdx.x, lane = tid & 31, wid = tid >> 5;
    int p = wid >> 2, nc = wid & 3;
    int rA = 16 * p, rB = 16 * (7 - p), n0 = 32 * nc;
    int l15 = lane & 15, lhi = (lane >> 4) << 3;

    u32 s0 = sb, s1 = sb + TILE_BYTES, s2 = sb + 2 * TILE_BYTES,
        s3 = sb + 3 * TILE_BYTES;
    u32 uSh = sb + 4 * TILE_BYTES, uSl = sb + 5 * TILE_BYTES;

    int qb  = blockIdx.x * 16384;
    int qb2 = (blockIdx.x + 128) * 16384;

    // initial loads: g1 = Q1 + S1; g2 = KT1
    copy_tile_async<512>(s0,  g_q_hi + qb, tid);
    copy_tile_async<512>(s1,  g_q_lo + qb, tid);
    copy_tile_async<512>(uSh, g_s_hi + qb, tid);
    copy_tile_async<512>(uSl, g_s_lo + qb, tid);
    cp_commit();
    copy_tile_async<512>(s2, g_kT_hi + qb, tid);
    copy_tile_async<512>(s3, g_kT_lo + qb, tid);
    cp_commit();
    cp_wait1();
    __syncthreads();

    for (int it = 0; it < 2; ++it) {
        // phase A: O = Qr @ S  (dense)
        float oacc[8][4] = {};
        gemm_pair(s0, s1, uSh, uSl, oacc, rA, rB, n0, 7, 7, lane);

        cp_wait0();        // KT arrived
        __syncthreads();   // S slots dead; KT visible

        // Vh into S_hi slot (streams under phase B); V_lo dropped (precision ok)
        copy_tile_async<512>(uSh, g_v_hi + qb, tid);
        cp_commit();

        // phase B: E blocks (g,j) from balanced LUT
        float eacc[3][2][4] = {};
        int un = UN[wid];
        #pragma unroll
        for (int u = 0; u < 3; ++u) {
            if (u < un) {
                int gU = UG[wid][u], jU = UJ[wid][u];
                int ra = 16 * gU, nb = 16 * jU;
                #pragma unroll 1
                for (int kk = 0; kk < 8; ++kk) {
                    u32 ar = (u32)(((ra + l15) * TPAD + kk * 16 + lhi) * 2);
                    u32 HA[4], LA[4];
                    ldsm4(HA, s0 + ar);
                    ldsm4(LA, s1 + ar);
                    u32 boff = (u32)(((kk * 16 + l15) * TPAD + nb + lhi) * 2);
                    u32 B[4], C[4];
                    ldsm4t(B, s2 + boff);
                    ldsm4t(C, s3 + boff);
                    float* a0 = eacc[u][0];
                    float* a1 = eacc[u][1];
                    mma_bf16(a0, HA, B[0], B[1]);
                    mma_bf16(a1, HA, B[2], B[3]);
                    mma_bf16(a0, HA, C[0], C[1]);
                    mma_bf16(a1, HA, C[2], C[3]);
                    mma_bf16(a0, LA, B[0], B[1]);
                    mma_bf16(a1, LA, B[2], B[3]);
                }
            }
        }
        __syncthreads();   // Q + KT reads complete

        // prefetch next tile's Q + S_hi (Q slots and S_lo slot are dead)
        if (it == 0) {
            copy_tile_async<512>(s0,  g_q_hi + qb2, tid);
            copy_tile_async<512>(s1,  g_q_lo + qb2, tid);
            copy_tile_async<512>(uSl, g_s_hi + qb2, tid);
            cp_commit();
        }

        // mask (diag blocks only) + split E -> s2 (hi), s3 (lo)
        {
            char* eh = (char*)0 + 0;   // placate compiler; use pointers below
            (void)eh;
            #pragma unroll
            for (int u = 0; u < 3; ++u) {
                if (u < un) {
                    int gU = UG[wid][u], jU = UJ[wid][u];
                    int rr0 = 16 * gU + (lane >> 2), rr1 = rr0 + 8;
                    bool diag = (jU == gU);
                    #pragma unroll
                    for (int h = 0; h < 2; ++h) {
                        float* a = eacc[u][h];
                        int c = 16 * jU + h * 8 + (lane & 3) * 2;
                        float v0 = (!diag || c     <= rr0) ? a[0] : 0.f;
                        float v1 = (!diag || c + 1 <= rr0) ? a[1] : 0.f;
                        float v2 = (!diag || c     <= rr1) ? a[2] : 0.f;
                        float v3 = (!diag || c + 1 <= rr1) ? a[3] : 0.f;
                        __nv_bfloat16 h0 = __float2bfloat16(v0);
                        __nv_bfloat16 h1 = __float2bfloat16(v1);
                        __nv_bfloat16 h2 = __float2bfloat16(v2);
                        __nv_bfloat16 h3 = __float2bfloat16(v3);
                        *(u32*)(sm + (s2 - sb) + (rr0 * TPAD + c) * 2) = packbf(h0, h1);
                        *(u32*)(sm + (s2 - sb) + (rr1 * TPAD + c) * 2) = packbf(h2, h3);
                        *(u32*)(sm + (s3 - sb) + (rr0 * TPAD + c) * 2) =
                            packbf(__float2bfloat16(v0 - __bfloat162float(h0)),
                                   __float2bfloat16(v1 - __bfloat162float(h1)));
                        *(u32*)(sm + (s3 - sb) + (rr1 * TPAD + c) * 2) =
                            packbf(__float2bfloat16(v2 - __bfloat162float(h2)),
                                   __float2bfloat16(v3 - __bfloat162float(h3)));
                    }
                }
            }
        }
        if (it == 0) cp_wait1();   // Vh done; (Q2,S2h) may still stream
        else         cp_wait0();   // Vh done
        __syncthreads();           // E + Vh visible

        // phase C: O += E @ Vh  (2-term, balanced causal)
        gemm_pair2(s2, s3, uSh, oacc, rA, rB, n0, p, 7 - p, lane);

        epilogue(out + qb, oacc, rA, rB, n0, lane);

        if (it == 0) {
            __syncthreads();   // all warps done with phase-C smem reads
            // next tile: S_lo -> old Vh slot; KT -> s2/s3
            copy_tile_async<512>(uSh, g_s_lo + qb2, tid);
            cp_commit();
            copy_tile_async<512>(s2, g_kT_hi + qb2, tid);
            copy_tile_async<512>(s3, g_kT_lo + qb2, tid);
            cp_commit();
            cp_wait1();        // (Q2,S2h) + S2l done; KT2 streaming
            __syncthreads();
            // swap S slot roles: S2h sits in uSl, S2l in uSh
            u32 t = uSh; uSh = uSl; uSl = t;
            qb = qb2;
        }
    }
}

// ---------------------------------------------------------------------------
extern "C" void kernel_launch(void* const* d_in, const int* in_sizes, int n_in,
                              void* d_out, int out_size) {
    (void)in_sizes; (void)n_in; (void)out_size;
    const float* Q = (const float*)d_in[0];
    const float* K = (const float*)d_in[1];
    const float* V = (const float*)d_in[2];
    float* out = (float*)d_out;

    cudaFuncSetAttribute(k_rope, cudaFuncAttributeMaxDynamicSharedMemorySize, 66048);
    cudaFuncSetAttribute(k_h,    cudaFuncAttributeMaxDynamicSharedMemorySize, 6 * TILE_BYTES);
    cudaFuncSetAttribute(k_out,  cudaFuncAttributeMaxDynamicSharedMemorySize, 6 * TILE_BYTES);

    k_tab <<<SL, 64>>>();
    k_rope<<<NT, 256, 66048>>>(Q, K, V);
    k_h   <<<128, 512, 6 * TILE_BYTES>>>();
    k_scan<<<dim3(NB, 64), 128>>>();
    k_out <<<128, 512, 6 * TILE_BYTES>>>(out);
}

// round 14
// speedup vs baseline: 1.2001x; 1.1032x over previous
#include <cuda_runtime.h>
#include <cuda_bf16.h>
#include <math.h>

#define NB 8
#define SL 4096
#define HD 128
#define CCH 128
#define NCH (SL / CCH)   // 32
#define NT  (NB * NCH)   // 256 tiles

#define TPAD 136                     // padded bf16 row stride in smem tiles
#define TILE_BYTES (128 * TPAD * 2)  // 34816

typedef unsigned int u32;

// ---------------------------------------------------------------------------
// Scratch (no allocations allowed)
// ---------------------------------------------------------------------------
__device__ float g_cos[SL * HD];
__device__ float g_sin[SL * HD];
__device__ float g_h  [NT * HD * HD];           // per-chunk H[d][e] fp32
__device__ __nv_bfloat16 g_q_hi [NT * 16384];   // Qr  [t][d]
__device__ __nv_bfloat16 g_q_lo [NT * 16384];
__device__ __nv_bfloat16 g_kT_hi[NT * 16384];   // Kr^T [d][t]
__device__ __nv_bfloat16 g_kT_lo[NT * 16384];
__device__ __nv_bfloat16 g_v_hi [NT * 16384];   // V   [t][e]
__device__ __nv_bfloat16 g_v_lo [NT * 16384];
__device__ __nv_bfloat16 g_s_hi [NT * 16384];   // S excl prefix [d][e]
__device__ __nv_bfloat16 g_s_lo [NT * 16384];

// Phase-B unit LUT: 36 causal E blocks (g,j), j<=g, spread so max 3 per warp.
__device__ __constant__ int UN[16]    = {3,3,2,3,2,2,2,2,2,3,2,2,2,2,3,1};
__device__ __constant__ int UG[16][3] = {{7,7,7},{7,7,7},{7,7,7},{6,6,6},
                                         {6,6,6},{6,6,6},{5,5,5},{5,5,5},
                                         {5,5,5},{4,4,4},{4,4,4},{3,3,3},
                                         {3,3,3},{2,2,2},{2,1,1},{0,0,0}};
__device__ __constant__ int UJ[16][3] = {{0,1,2},{3,4,5},{6,7,7},{0,1,2},
                                         {3,4,4},{5,6,6},{0,1,1},{2,3,3},
                                         {4,5,5},{0,1,2},{3,4,4},{0,1,1},
                                         {2,3,3},{0,1,1},{2,0,1},{0,0,0}};

// ---------------------------------------------------------------------------
// Primitives (baseline PTX, valid on plain sm_100)
// ---------------------------------------------------------------------------
__device__ __forceinline__ u32 smem_u32(const void* p) {
    u32 a;
    asm("{ .reg .u64 t; cvta.to.shared.u64 t, %1; cvt.u32.u64 %0, t; }"
        : "=r"(a) : "l"(p));
    return a;
}
__device__ __forceinline__ void ldsm4(u32* r, u32 a) {
    asm volatile("ldmatrix.sync.aligned.m8n8.x4.shared.b16 {%0,%1,%2,%3}, [%4];"
                 : "=r"(r[0]), "=r"(r[1]), "=r"(r[2]), "=r"(r[3]) : "r"(a));
}
__device__ __forceinline__ void ldsm4t(u32* r, u32 a) {
    asm volatile("ldmatrix.sync.aligned.m8n8.x4.trans.shared.b16 {%0,%1,%2,%3}, [%4];"
                 : "=r"(r[0]), "=r"(r[1]), "=r"(r[2]), "=r"(r[3]) : "r"(a));
}
__device__ __forceinline__ void mma_bf16(float* c, const u32* a, u32 b0, u32 b1) {
    asm volatile(
        "mma.sync.aligned.m16n8k16.row.col.f32.bf16.bf16.f32 "
        "{%0,%1,%2,%3},{%4,%5,%6,%7},{%8,%9},{%0,%1,%2,%3};"
        : "+f"(c[0]), "+f"(c[1]), "+f"(c[2]), "+f"(c[3])
        : "r"(a[0]), "r"(a[1]), "r"(a[2]), "r"(a[3]), "r"(b0), "r"(b1));
}
__device__ __forceinline__ void cp16(u32 dst, const void* src) {
    asm volatile("cp.async.cg.shared.global [%0], [%1], 16;"
                 :: "r"(dst), "l"(src) : "memory");
}
__device__ __forceinline__ void cp_commit() {
    asm volatile("cp.async.commit_group;" ::: "memory");
}
__device__ __forceinline__ void cp_wait0() {
    asm volatile("cp.async.wait_group 0;" ::: "memory");
}
__device__ __forceinline__ void cp_wait1() {
    asm volatile("cp.async.wait_group 1;" ::: "memory");
}
__device__ __forceinline__ u32 packbf(__nv_bfloat16 lo, __nv_bfloat16 hi) {
    return (u32)__bfloat16_as_ushort(hi) << 16 | (u32)__bfloat16_as_ushort(lo);
}
__device__ __forceinline__ void split_store(__nv_bfloat16* hi, __nv_bfloat16* lo,
                                            int off, float v) {
    __nv_bfloat16 h = __float2bfloat16(v);
    hi[off] = h;
    lo[off] = __float2bfloat16(v - __bfloat162float(h));
}
// split 8 floats -> hi/lo bf16, one uint4 store each
__device__ __forceinline__ void split8_store(__nv_bfloat16* ghi, __nv_bfloat16* glo,
                                             int off, const float* v) {
    u32 hw[4], lw[4];
    #pragma unroll
    for (int j = 0; j < 4; ++j) {
        float f0 = v[2 * j], f1 = v[2 * j + 1];
        __nv_bfloat16 h0 = __float2bfloat16(f0), h1 = __float2bfloat16(f1);
        hw[j] = packbf(h0, h1);
        lw[j] = packbf(__float2bfloat16(f0 - __bfloat162float(h0)),
                       __float2bfloat16(f1 - __bfloat162float(h1)));
    }
    *(uint4*)(ghi + off) = *(uint4*)hw;
    *(uint4*)(glo + off) = *(uint4*)lw;
}
__device__ __forceinline__ void ld8(float* r, const float* p) {
    *(float4*)r       = *(const float4*)p;
    *(float4*)(r + 4) = *(const float4*)(p + 4);
}

// gmem [128][128] bf16 tile -> padded smem tile, via cp.async (NTHR threads)
template<int NTHR>
__device__ __forceinline__ void copy_tile_async(u32 dst, const __nv_bfloat16* src,
                                                int tid) {
    #pragma unroll
    for (int i = 0; i < 2048 / NTHR; ++i) {
        int j = tid + i * NTHR;
        int row = j >> 4, col = j & 15;
        cp16(dst + row * (TPAD * 2) + col * 16, (const char*)src + j * 16);
    }
}

// ---------------------------------------------------------------------------
// Paired-row-group 3-term split GEMM, warp tile = rows {rA:16, rB:16} x 32
// cols (2 nt blocks at n0). Group A active for kk<=kkA, group B for kk<=kkB.
// acc[8][4]: frag idx = grp*4 + nt*2 + h.
// ---------------------------------------------------------------------------
__device__ __forceinline__ void gemm_pair(u32 ah, u32 al, u32 bh, u32 bl,
                                          float acc[8][4], int rA, int rB, int n0,
                                          int kkA, int kkB, int lane) {
    int l15 = lane & 15, lhi = (lane >> 4) << 3;
    #pragma unroll 1
    for (int kk = 0; kk <= kkB; ++kk) {
        u32 arB = (u32)(((rB + l15) * TPAD + kk * 16 + lhi) * 2);
        u32 HB[4], LB[4];
        ldsm4(HB, ah + arB);
        ldsm4(LB, al + arB);
        bool doA = (kk <= kkA);
        u32 HA[4], LA[4];
        if (doA) {
            u32 arA = (u32)(((rA + l15) * TPAD + kk * 16 + lhi) * 2);
            ldsm4(HA, ah + arA);
            ldsm4(LA, al + arA);
        }
        #pragma unroll
        for (int nt = 0; nt < 2; ++nt) {
            u32 boff = (u32)(((kk * 16 + l15) * TPAD + n0 + nt * 16 + lhi) * 2);
            u32 B[4], C[4];
            ldsm4t(B, bh + boff);
            ldsm4t(C, bl + boff);
            float* b0 = acc[4 + nt * 2];
            float* b1 = acc[4 + nt * 2 + 1];
            mma_bf16(b0, HB, B[0], B[1]);
            mma_bf16(b1, HB, B[2], B[3]);
            mma_bf16(b0, HB, C[0], C[1]);
            mma_bf16(b1, HB, C[2], C[3]);
            mma_bf16(b0, LB, B[0], B[1]);
            mma_bf16(b1, LB, B[2], B[3]);
            if (doA) {
                float* a0 = acc[nt * 2];
                float* a1 = acc[nt * 2 + 1];
                mma_bf16(a0, HA, B[0], B[1]);
                mma_bf16(a1, HA, B[2], B[3]);
                mma_bf16(a0, HA, C[0], C[1]);
                mma_bf16(a1, HA, C[2], C[3]);
                mma_bf16(a0, LA, B[0], B[1]);
                mma_bf16(a1, LA, B[2], B[3]);
            }
        }
    }
}

// 2-term variant: A split (ah, al), B single (bh). Used for phase C (E @ Vh).
__device__ __forceinline__ void gemm_pair2(u32 ah, u32 al, u32 bh,
                                           float acc[8][4], int rA, int rB, int n0,
                                           int kkA, int kkB, int lane) {
    int l15 = lane & 15, lhi = (lane >> 4) << 3;
    #pragma unroll 1
    for (int kk = 0; kk <= kkB; ++kk) {
        u32 arB = (u32)(((rB + l15) * TPAD + kk * 16 + lhi) * 2);
        u32 HB[4], LB[4];
        ldsm4(HB, ah + arB);
        ldsm4(LB, al + arB);
        bool doA = (kk <= kkA);
        u32 HA[4], LA[4];
        if (doA) {
            u32 arA = (u32)(((rA + l15) * TPAD + kk * 16 + lhi) * 2);
            ldsm4(HA, ah + arA);
            ldsm4(LA, al + arA);
        }
        #pragma unroll
        for (int nt = 0; nt < 2; ++nt) {
            u32 boff = (u32)(((kk * 16 + l15) * TPAD + n0 + nt * 16 + lhi) * 2);
            u32 B[4];
            ldsm4t(B, bh + boff);
            float* b0 = acc[4 + nt * 2];
            float* b1 = acc[4 + nt * 2 + 1];
            mma_bf16(b0, HB, B[0], B[1]);
            mma_bf16(b1, HB, B[2], B[3]);
            mma_bf16(b0, LB, B[0], B[1]);
            mma_bf16(b1, LB, B[2], B[3]);
            if (doA) {
                float* a0 = acc[nt * 2];
                float* a1 = acc[nt * 2 + 1];
                mma_bf16(a0, HA, B[0], B[1]);
                mma_bf16(a1, HA, B[2], B[3]);
                mma_bf16(a0, LA, B[0], B[1]);
                mma_bf16(a1, LA, B[2], B[3]);
            }
        }
    }
}

// acc -> gmem fp32 [128][128] tile (row groups rA/rB, cols n0..n0+31)
__device__ __forceinline__ void epilogue(float* dst, float acc[8][4],
                                         int rA, int rB, int n0, int lane) {
    int rr = lane >> 2, cb = n0 + (lane & 3) * 2;
    #pragma unroll
    for (int grp = 0; grp < 2; ++grp) {
        int base = grp ? rB : rA;
        #pragma unroll
        for (int nt = 0; nt < 2; ++nt)
            #pragma unroll
            for (int h = 0; h < 2; ++h) {
                float* a = acc[grp * 4 + nt * 2 + h];
                int r0 = base + rr, c = cb + nt * 16 + h * 8;
                *(float2*)(dst + r0 * 128 + c)       = make_float2(a[0], a[1]);
                *(float2*)(dst + (r0 + 8) * 128 + c) = make_float2(a[2], a[3]);
            }
    }
}

// ---------------------------------------------------------------------------
// Kernel 0: RoPE cos/sin table (64 threads/row; halves mirror at d^64)
// ---------------------------------------------------------------------------
__global__ void k_tab() {
    int s = blockIdx.x;
    int j = threadIdx.x;   // 0..63
    double inv = exp(-(double)j * (log(10000.0) / 64.0));
    double a = (double)s * inv;
    double sv, cv;
    sincos(a, &sv, &cv);
    float cf = (float)cv, sf = (float)sv;
    g_cos[s * HD + j]      = cf;
    g_cos[s * HD + j + 64] = cf;
    g_sin[s * HD + j]      = sf;
    g_sin[s * HD + j + 64] = sf;
}

// ---------------------------------------------------------------------------
// Kernel 1: RoPE + split-bf16, mirror-paired: each thread owns octets
// (d0, d0+64) so every Q/K/V element and table entry is loaded exactly once.
// Q -> g_q [t][d]; K -> g_kT [d][t]; V -> g_v [t][e].
// ---------------------------------------------------------------------------
__global__ void __launch_bounds__(256) k_rope(const float* __restrict__ Q,
                                              const float* __restrict__ K,
                                              const float* __restrict__ V) {
    extern __shared__ float buf[];   // [128][129]
    int b  = blockIdx.x >> 5;
    int ch = blockIdx.x & 31;
    int tid = threadIdx.x;
    int base  = (b * SL + ch * CCH) * HD;
    int tbase = blockIdx.x * 16384;

    #pragma unroll
    for (int i = 0; i < 4; ++i) {
        int u = tid + i * 256;          // 0..1023
        int t = u >> 3;                 // row 0..127
        int d0 = (u & 7) << 3;          // octet in lower half: 0..56
        int dp = d0 + 64;
        int s = ch * CCH + t;

        float cs[8], sn[8], q0[8], q1[8], k0[8], k1[8], v0[8], v1[8];
        ld8(cs, g_cos + s * HD + d0);   // == table at dp (mirror)
        ld8(sn, g_sin + s * HD + d0);
        ld8(q0, Q + base + t * HD + d0);
        ld8(q1, Q + base + t * HD + dp);
        ld8(k0, K + base + t * HD + d0);
        ld8(k1, K + base + t * HD + dp);
        ld8(v0, V + base + t * HD + d0);
        ld8(v1, V + base + t * HD + dp);

        float qa[8], qb[8], ka[8], kb[8];
        #pragma unroll
        for (int j = 0; j < 8; ++j) {
            qa[j] = q0[j] * cs[j] - q1[j] * sn[j];
            qb[j] = q1[j] * cs[j] + q0[j] * sn[j];
            ka[j] = k0[j] * cs[j] - k1[j] * sn[j];
            kb[j] = k1[j] * cs[j] + k0[j] * sn[j];
        }
        split8_store(g_q_hi, g_q_lo, tbase + t * HD + d0, qa);
        split8_store(g_q_hi, g_q_lo, tbase + t * HD + dp, qb);
        split8_store(g_v_hi, g_v_lo, tbase + t * HD + d0, v0);
        split8_store(g_v_hi, g_v_lo, tbase + t * HD + dp, v1);
        #pragma unroll
        for (int j = 0; j < 8; ++j) {
            buf[t * 129 + d0 + j] = ka[j];
            buf[t * 129 + dp + j] = kb[j];
        }
    }
    __syncthreads();

    #pragma unroll
    for (int i = 0; i < 8; ++i) {
        int u = tid + i * 256;
        int d = u >> 4;
        int t0 = (u & 15) << 3;
        float kv[8];
        #pragma unroll
        for (int j = 0; j < 8; ++j) kv[j] = buf[(t0 + j) * 129 + d];
        split8_store(g_kT_hi, g_kT_lo, tbase + d * HD + t0, kv);
    }
}

// ---------------------------------------------------------------------------
// Kernel 2: per-chunk H[d][e] = sum_t Kr^T[d][t] * V[t][e]. Dense, 3-term.
// Persistent: grid 128, tiles (bx, bx+128). KT2 prefetch streams under
// tile-1 gemm; V2 prefetch streams under tile-1 epilogue.
// ---------------------------------------------------------------------------
__global__ void __launch_bounds__(512) k_h() {
    extern __shared__ char sm[];
    u32 sb = smem_u32(sm);
    int tid = threadIdx.x, lane = tid & 31, wid = tid >> 5;
    int p = wid >> 2, nc = wid & 3;
    int rA = 16 * p, rB = 16 * (7 - p), n0 = 32 * nc;
    int tb1 = blockIdx.x * 16384, tb2 = (blockIdx.x + 128) * 16384;

    u32 a0 = sb, a1 = sb + TILE_BYTES, a2 = sb + 2 * TILE_BYTES,
        a3 = sb + 3 * TILE_BYTES, p0 = sb + 4 * TILE_BYTES, p1 = sb + 5 * TILE_BYTES;

    // g1: tile-1 operands
    copy_tile_async<512>(a0, g_kT_hi + tb1, tid);
    copy_tile_async<512>(a1, g_kT_lo + tb1, tid);
    copy_tile_async<512>(a2, g_v_hi  + tb1, tid);
    copy_tile_async<512>(a3, g_v_lo  + tb1, tid);
    cp_commit();
    // g2: tile-2 KT prefetch (streams under tile-1 gemm)
    copy_tile_async<512>(p0, g_kT_hi + tb2, tid);
    copy_tile_async<512>(p1, g_kT_lo + tb2, tid);
    cp_commit();

    cp_wait1();
    __syncthreads();

    float acc[8][4] = {};
    gemm_pair(a0, a1, a2, a3, acc, rA, rB, n0, 7, 7, lane);
    __syncthreads();   // all warps done reading V slots

    // tile-2 V prefetch streams under tile-1 epilogue
    copy_tile_async<512>(a2, g_v_hi + tb2, tid);
    copy_tile_async<512>(a3, g_v_lo + tb2, tid);
    cp_commit();

    epilogue(g_h + tb1, acc, rA, rB, n0, lane);

    cp_wait0();
    __syncthreads();

    float acc2[8][4] = {};
    gemm_pair(p0, p1, a2, a3, acc2, rA, rB, n0, 7, 7, lane);
    epilogue(g_h + tb2, acc2, rA, rB, n0, lane);
}

// ---------------------------------------------------------------------------
// Kernel 3: exclusive prefix scan of H over chunks -> split-bf16 S tiles.
// R8-proven form: 1024 blocks, thread = one column, full-MLP prefetch.
// ---------------------------------------------------------------------------
__global__ void __launch_bounds__(128) k_scan() {
    int b = blockIdx.x, d = blockIdx.y, e = threadIdx.x;
    float vals[NCH];
    #pragma unroll
    for (int i = 0; i < NCH; ++i)
        vals[i] = g_h[(b * NCH + i) * 16384 + d * 128 + e];
    int o = d * 128 + e;
    float run = 0.f;
    #pragma unroll
    for (int i = 0; i < NCH; ++i) {
        int tb = (b * NCH + i) * 16384;
        split_store(g_s_hi, g_s_lo, tb + o, run);
        run += vals[i];
    }
}

// ---------------------------------------------------------------------------
// Kernel 4: out = tril(Qr Kr^T) V + Qr S. Persistent: grid 128, 2 tiles/CTA.
// Slots: s0/s1 = Q, s2/s3 = KT -> E, uSh/uSl = S -> Vh (roles swap between
// tiles). Phase C = 2-term (Eh+El) @ Vh. Cross-tile prefetch: Q2+S2h during
// E-split; S2l + KT2 issued before tile-1 epilogue (stream under STG).
// ---------------------------------------------------------------------------
__global__ void __launch_bounds__(512) k_out(float* __restrict__ out) {
    extern __shared__ char sm[];
    u32 sb = smem_u32(sm);
    int tid = threadIdx.x, lane = tid & 31, wid = tid >> 5;
    int p = wid >> 2, nc = wid & 3;
    int rA = 16 * p, rB = 16 * (7 - p), n0 = 32 * nc;
    int l15 = lane & 15, lhi = (lane >> 4) << 3;

    u32 s0 = sb, s1 = sb + TILE_BYTES, s2 = sb + 2 * TILE_BYTES,
        s3 = sb + 3 * TILE_BYTES;
    u32 uSh = sb + 4 * TILE_BYTES, uSl = sb + 5 * TILE_BYTES;

    int qb  = blockIdx.x * 16384;
    int qb2 = (blockIdx.x + 128) * 16384;

    // initial loads: g1 = Q1 + S1; g2 = KT1
    copy_tile_async<512>(s0,  g_q_hi + qb, tid);
    copy_tile_async<512>(s1,  g_q_lo + qb, tid);
    copy_tile_async<512>(uSh, g_s_hi + qb, tid);
    copy_tile_async<512>(uSl, g_s_lo + qb, tid);
    cp_commit();
    copy_tile_async<512>(s2, g_kT_hi + qb, tid);
    copy_tile_async<512>(s3, g_kT_lo + qb, tid);
    cp_commit();
    cp_wait1();
    __syncthreads();

    for (int it = 0; it < 2; ++it) {
        // phase A: O = Qr @ S  (dense)
        float oacc[8][4] = {};
        gemm_pair(s0, s1, uSh, uSl, oacc, rA, rB, n0, 7, 7, lane);

        cp_wait0();        // KT arrived
        __syncthreads();   // S slots dead; KT visible

        // Vh into S_hi slot (streams under phase B)
        copy_tile_async<512>(uSh, g_v_hi + qb, tid);
        cp_commit();

        // phase B: E blocks (g,j) from balanced LUT
        float eacc[3][2][4] = {};
        int un = UN[wid];
        #pragma unroll
        for (int u = 0; u < 3; ++u) {
            if (u < un) {
                int gU = UG[wid][u], jU = UJ[wid][u];
                int ra = 16 * gU, nb = 16 * jU;
                #pragma unroll 1
                for (int kk = 0; kk < 8; ++kk) {
                    u32 ar = (u32)(((ra + l15) * TPAD + kk * 16 + lhi) * 2);
                    u32 HA[4], LA[4];
                    ldsm4(HA, s0 + ar);
                    ldsm4(LA, s1 + ar);
                    u32 boff = (u32)(((kk * 16 + l15) * TPAD + nb + lhi) * 2);
                    u32 B[4], C[4];
                    ldsm4t(B, s2 + boff);
                    ldsm4t(C, s3 + boff);
                    float* a0 = eacc[u][0];
                    float* a1 = eacc[u][1];
                    mma_bf16(a0, HA, B[0], B[1]);
                    mma_bf16(a1, HA, B[2], B[3]);
                    mma_bf16(a0, HA, C[0], C[1]);
                    mma_bf16(a1, HA, C[2], C[3]);
                    mma_bf16(a0, LA, B[0], B[1]);
                    mma_bf16(a1, LA, B[2], B[3]);
                }
            }
        }
        __syncthreads();   // Q + KT reads complete

        // prefetch next tile's Q + S_hi (Q slots and S_lo slot are dead)
        if (it == 0) {
            copy_tile_async<512>(s0,  g_q_hi + qb2, tid);
            copy_tile_async<512>(s1,  g_q_lo + qb2, tid);
            copy_tile_async<512>(uSl, g_s_hi + qb2, tid);
            cp_commit();
        }

        // mask (diag blocks only) + split E -> s2 (hi), s3 (lo)
        #pragma unroll
        for (int u = 0; u < 3; ++u) {
            if (u < un) {
                int gU = UG[wid][u], jU = UJ[wid][u];
                int rr0 = 16 * gU + (lane >> 2), rr1 = rr0 + 8;
                bool diag = (jU == gU);
                #pragma unroll
                for (int h = 0; h < 2; ++h) {
                    float* a = eacc[u][h];
                    int c = 16 * jU + h * 8 + (lane & 3) * 2;
                    float v0 = (!diag || c     <= rr0) ? a[0] : 0.f;
                    float v1 = (!diag || c + 1 <= rr0) ? a[1] : 0.f;
                    float v2 = (!diag || c     <= rr1) ? a[2] : 0.f;
                    float v3 = (!diag || c + 1 <= rr1) ? a[3] : 0.f;
                    __nv_bfloat16 h0 = __float2bfloat16(v0);
                    __nv_bfloat16 h1 = __float2bfloat16(v1);
                    __nv_bfloat16 h2 = __float2bfloat16(v2);
                    __nv_bfloat16 h3 = __float2bfloat16(v3);
                    *(u32*)(sm + (s2 - sb) + (rr0 * TPAD + c) * 2) = packbf(h0, h1);
                    *(u32*)(sm + (s2 - sb) + (rr1 * TPAD + c) * 2) = packbf(h2, h3);
                    *(u32*)(sm + (s3 - sb) + (rr0 * TPAD + c) * 2) =
                        packbf(__float2bfloat16(v0 - __bfloat162float(h0)),
                               __float2bfloat16(v1 - __bfloat162float(h1)));
                    *(u32*)(sm + (s3 - sb) + (rr1 * TPAD + c) * 2) =
                        packbf(__float2bfloat16(v2 - __bfloat162float(h2)),
                               __float2bfloat16(v3 - __bfloat162float(h3)));
                }
            }
        }
        if (it == 0) cp_wait1();   // Vh done; (Q2,S2h) may still stream
        else         cp_wait0();   // Vh done
        __syncthreads();           // E + Vh visible

        // phase C: O += E @ Vh  (2-term, balanced causal)
        gemm_pair2(s2, s3, uSh, oacc, rA, rB, n0, p, 7 - p, lane);

        if (it == 0) {
            __syncthreads();       // phase-C smem reads complete
            // next tile: S_lo -> old Vh slot; KT -> s2/s3 (stream under epilogue)
            copy_tile_async<512>(uSh, g_s_lo + qb2, tid);
            cp_commit();
            copy_tile_async<512>(s2, g_kT_hi + qb2, tid);
            copy_tile_async<512>(s3, g_kT_lo + qb2, tid);
            cp_commit();
        }

        epilogue(out + qb, oacc, rA, rB, n0, lane);

        if (it == 0) {
            cp_wait1();            // (Q2,S2h) + S2l done; KT2 streaming
            __syncthreads();
            // swap S slot roles: S2h sits in uSl, S2l in uSh
            u32 t = uSh; uSh = uSl; uSl = t;
            qb = qb2;
        }
    }
}

// ---------------------------------------------------------------------------
extern "C" void kernel_launch(void* const* d_in, const int* in_sizes, int n_in,
                              void* d_out, int out_size) {
    (void)in_sizes; (void)n_in; (void)out_size;
    const float* Q = (const float*)d_in[0];
    const float* K = (const float*)d_in[1];
    const float* V = (const float*)d_in[2];
    float* out = (float*)d_out;

    cudaFuncSetAttribute(k_rope, cudaFuncAttributeMaxDynamicSharedMemorySize, 66048);
    cudaFuncSetAttribute(k_h,    cudaFuncAttributeMaxDynamicSharedMemorySize, 6 * TILE_BYTES);
    cudaFuncSetAttribute(k_out,  cudaFuncAttributeMaxDynamicSharedMemorySize, 6 * TILE_BYTES);

    k_tab <<<SL, 64>>>();
    k_rope<<<NT, 256, 66048>>>(Q, K, V);
    k_h   <<<128, 512, 6 * TILE_BYTES>>>();
    k_scan<<<dim3(NB, HD), 128>>>();
    k_out <<<128, 512, 6 * TILE_BYTES>>>(out);
}